// round 3
// baseline (speedup 1.0000x reference)
#include <cuda_runtime.h>
#include <cuda_bf16.h>
#include <math.h>

#define N_ENTITY 64368
#define N_REL    46
#define NBASES   8
#define DDIM     128
#define E_EDGES  600000
#define B_USERS  64
#define L_CTX    50
#define NE_ENT   256

// Scratch (device globals — allocation is forbidden)
__device__ __align__(16) float g_kg[N_ENTITY * DDIM];   // 33 MB: kg_emb accumulator
__device__ int g_deg[N_ENTITY * N_REL];                 // 11.8 MB: per-(dst,rel) degree

// ---------------------------------------------------------------------------
// Kernel 1: init kg_emb = root + bias, zero degree table
// ---------------------------------------------------------------------------
__global__ void k_init(const float* __restrict__ root, const float* __restrict__ bias) {
    const int stride = gridDim.x * blockDim.x;
    const int tid = blockIdx.x * blockDim.x + threadIdx.x;
    for (int i = tid; i < N_ENTITY * DDIM; i += stride)
        g_kg[i] = root[i] + bias[i & (DDIM - 1)];
    for (int i = tid; i < N_ENTITY * N_REL; i += stride)
        g_deg[i] = 0;
}

// ---------------------------------------------------------------------------
// Kernel 2: degree count per (dst, rel) segment
// ---------------------------------------------------------------------------
__global__ void k_deg(const int* __restrict__ edge_index, const int* __restrict__ edge_type) {
    int e = blockIdx.x * blockDim.x + threadIdx.x;
    if (e >= E_EDGES) return;
    int dst = edge_index[E_EDGES + e];
    int rel = edge_type[e];
    atomicAdd(&g_deg[dst * N_REL + rel], 1);
}

// ---------------------------------------------------------------------------
// Kernel 3: per-edge message + normalized scatter-add (warp per edge)
//   msg[d] = sum_b comp[rel,b] * basis[b][src][d];  kg[dst] += msg / deg
// ---------------------------------------------------------------------------
__global__ void __launch_bounds__(256) k_edge(const int* __restrict__ edge_index,
                                              const int* __restrict__ edge_type,
                                              const float* __restrict__ comp,
                                              const float* __restrict__ basis) {
    int warp = (blockIdx.x * blockDim.x + threadIdx.x) >> 5;
    int lane = threadIdx.x & 31;
    if (warp >= E_EDGES) return;

    int src = 0, dst = 0, rel = 0; float norm = 0.f;
    if (lane == 0) {
        src = edge_index[warp];
        dst = edge_index[E_EDGES + warp];
        rel = edge_type[warp];
        int dg = g_deg[dst * N_REL + rel];
        norm = 1.0f / (float)max(dg, 1);
    }
    src  = __shfl_sync(0xFFFFFFFFu, src, 0);
    dst  = __shfl_sync(0xFFFFFFFFu, dst, 0);
    rel  = __shfl_sync(0xFFFFFFFFu, rel, 0);
    norm = __shfl_sync(0xFFFFFFFFu, norm, 0);

    // Each lane owns 4 contiguous floats: one coalesced 512B row per basis
    const float4* bp = reinterpret_cast<const float4*>(basis) + (size_t)src * 32 + lane;
    const float* cr = comp + rel * NBASES;

    float4 acc = make_float4(0.f, 0.f, 0.f, 0.f);
#pragma unroll
    for (int b = 0; b < NBASES; b++) {
        float c = cr[b];                                 // broadcast (L1-resident)
        float4 v = bp[(size_t)b * N_ENTITY * 32];
        acc.x += c * v.x; acc.y += c * v.y; acc.z += c * v.z; acc.w += c * v.w;
    }
    acc.x *= norm; acc.y *= norm; acc.z *= norm; acc.w *= norm;

    float* p = &g_kg[dst * DDIM + lane * 4];
    atomicAdd(p + 0, acc.x);
    atomicAdd(p + 1, acc.y);
    atomicAdd(p + 2, acc.z);
    atomicAdd(p + 3, acc.w);
}

// ---------------------------------------------------------------------------
// Kernel 4: self-attention over context + user projection MLP (1 block/user)
// ---------------------------------------------------------------------------
__global__ void __launch_bounds__(DDIM) k_user(const int* __restrict__ ctx,
                       const int* __restrict__ cmask,
                       const float* __restrict__ attn_W,
                       const float* __restrict__ attn_b,
                       const float* __restrict__ fc1_W, const float* __restrict__ fc1_b,
                       const float* __restrict__ fc2_W, const float* __restrict__ fc2_b,
                       float* __restrict__ out) {
    __shared__ float h[L_CTX][DDIM];
    __shared__ float sc[L_CTX];
    __shared__ float attn[L_CTX];
    __shared__ float urep[DDIM];
    __shared__ float yv[DDIM];

    int b = blockIdx.x;
    int t = threadIdx.x;           // 128 threads
    int wid = t >> 5, lane = t & 31;

    // gather h = kg_emb[context_entities[b]]
    for (int l = 0; l < L_CTX; l++) {
        int ent = ctx[b * L_CTX + l];
        h[l][t] = g_kg[ent * DDIM + t];
    }
    __syncthreads();

    // scores: sc[l] = sum_d tanh( (h[l] @ W)[d] ) * ab[d]   (warp per l)
    for (int l = wid; l < L_CTX; l += 4) {
        float acc = 0.f;
#pragma unroll
        for (int j = 0; j < 4; j++) {
            int d = lane + j * 32;
            float u = 0.f;
            for (int k = 0; k < DDIM; k++)
                u += h[l][k] * attn_W[k * DDIM + d];
            acc += tanhf(u) * attn_b[d];
        }
#pragma unroll
        for (int o = 16; o; o >>= 1) acc += __shfl_xor_sync(0xFFFFFFFFu, acc, o);
        if (lane == 0) sc[l] = acc;
    }
    __syncthreads();

    // masked softmax (serial on thread 0 — 50 elements, negligible)
    if (t == 0) {
        float mx = -3.4e38f; bool any = false;
        for (int l = 0; l < L_CTX; l++)
            if (cmask[b * L_CTX + l]) { any = true; mx = fmaxf(mx, sc[l]); }
        float s = 0.f;
        for (int l = 0; l < L_CTX; l++) {
            float v = cmask[b * L_CTX + l] ? expf(sc[l] - mx) : 0.f;
            attn[l] = v; s += v;
        }
        float inv = any ? 1.f / s : 0.f;
        for (int l = 0; l < L_CTX; l++) attn[l] *= inv;
    }
    __syncthreads();

    // user_rep[t] = sum_l attn[l] * h[l][t]
    float r = 0.f;
    for (int l = 0; l < L_CTX; l++) r += attn[l] * h[l][t];
    urep[t] = r;
    __syncthreads();

    // MLP: relu(u @ fc1 + b1) @ fc2 + b2
    float y = fc1_b[t];
    for (int k = 0; k < DDIM; k++) y += urep[k] * fc1_W[k * DDIM + t];
    yv[t] = fmaxf(y, 0.f);
    __syncthreads();

    float o = fc2_b[t];
    for (int k = 0; k < DDIM; k++) o += yv[k] * fc2_W[k * DDIM + t];
    out[b * DDIM + t] = o;
}

// ---------------------------------------------------------------------------
// Kernel 5: entity gather + projection MLP (1 block/entity)
// ---------------------------------------------------------------------------
__global__ void __launch_bounds__(DDIM) k_entity(const int* __restrict__ entity_ids,
                         const float* __restrict__ efc1_W, const float* __restrict__ efc1_b,
                         const float* __restrict__ efc2_W, const float* __restrict__ efc2_b,
                         float* __restrict__ out) {
    __shared__ float x[DDIM];
    __shared__ float yv[DDIM];
    int i = blockIdx.x;
    int t = threadIdx.x;

    int ent = entity_ids[i];
    x[t] = g_kg[ent * DDIM + t];
    __syncthreads();

    float y = efc1_b[t];
    for (int k = 0; k < DDIM; k++) y += x[k] * efc1_W[k * DDIM + t];
    yv[t] = fmaxf(y, 0.f);
    __syncthreads();

    float o = efc2_b[t];
    for (int k = 0; k < DDIM; k++) o += yv[k] * efc2_W[k * DDIM + t];
    out[B_USERS * DDIM + i * DDIM + t] = o;
}

// ---------------------------------------------------------------------------
extern "C" void kernel_launch(void* const* d_in, const int* in_sizes, int n_in,
                              void* d_out, int out_size) {
    const int*   edge_index = (const int*)d_in[0];    // [2, E]
    const int*   edge_type  = (const int*)d_in[1];    // [E]
    const int*   ctx        = (const int*)d_in[2];    // [B, L]
    const int*   cmask      = (const int*)d_in[3];    // [B, L] (bool -> int32)
    const int*   entity_ids = (const int*)d_in[4];    // [NE]
    const float* comp       = (const float*)d_in[5];  // [46, 8]
    const float* basis      = (const float*)d_in[6];  // [8, N, 128]
    const float* root       = (const float*)d_in[7];  // [N, 128]
    const float* bias       = (const float*)d_in[8];  // [128]
    const float* attn_W     = (const float*)d_in[9];
    const float* attn_b     = (const float*)d_in[10];
    const float* fc1_W      = (const float*)d_in[11];
    const float* fc1_b      = (const float*)d_in[12];
    const float* fc2_W      = (const float*)d_in[13];
    const float* fc2_b      = (const float*)d_in[14];
    const float* efc1_W     = (const float*)d_in[15];
    const float* efc1_b     = (const float*)d_in[16];
    const float* efc2_W     = (const float*)d_in[17];
    const float* efc2_b     = (const float*)d_in[18];
    float* out = (float*)d_out;

    k_init<<<2048, 256>>>(root, bias);
    k_deg<<<(E_EDGES + 255) / 256, 256>>>(edge_index, edge_type);
    k_edge<<<(E_EDGES * 32 + 255) / 256, 256>>>(edge_index, edge_type, comp, basis);
    k_user<<<B_USERS, DDIM>>>(ctx, cmask, attn_W, attn_b,
                              fc1_W, fc1_b, fc2_W, fc2_b, out);
    k_entity<<<NE_ENT, DDIM>>>(entity_ids, efc1_W, efc1_b, efc2_W, efc2_b, out);
}

// round 5
// speedup vs baseline: 1.6289x; 1.6289x over previous
#include <cuda_runtime.h>
#include <cuda_bf16.h>
#include <math.h>

#define N_ENTITY 64368
#define N_REL    46
#define NBASES   8
#define DDIM     128
#define E_EDGES  600000
#define B_USERS  64
#define L_CTX    50
#define NE_ENT   256

#define SCAN_BLK   256
#define SCAN_GRID  ((N_ENTITY + SCAN_BLK - 1) / SCAN_BLK)   // 252
#define HPAD       (SCAN_GRID * SCAN_BLK)                   // 64512

// ---- device-global scratch (allocation is forbidden; int atomics only) ----
__device__ __align__(16) float  g_kg[N_ENTITY * DDIM];      // 33 MB final kg_emb
__device__ __align__(16) float4 g_msg4[(size_t)E_EDGES * 32]; // 307 MB messages (dst-sorted)
__device__ int   g_deg[N_ENTITY * N_REL];                   // per-(dst,rel) degree
__device__ int   g_hist[2 * HPAD];                          // [0]=per-src, [1]=per-dst counts
__device__ int   g_offA[N_ENTITY + 1];                      // src-sorted offsets
__device__ int   g_offB[N_ENTITY + 1];                      // dst-sorted offsets
__device__ int   g_cur[2 * N_ENTITY];                       // scatter cursors
__device__ int   g_bsum[2 * SCAN_GRID];                     // scan partials
__device__ int   g_edst[E_EDGES];                           // src-sorted: dst | (rel<<16)
__device__ int   g_epos[E_EDGES];                           // src-sorted: dst-sorted slot
__device__ float g_sc[B_USERS * L_CTX];                     // attention scores

// ---------------------------------------------------------------------------
// zero deg + both histograms
// ---------------------------------------------------------------------------
__global__ void k_init() {
    const int stride = gridDim.x * blockDim.x;
    const int tid = blockIdx.x * blockDim.x + threadIdx.x;
    for (int i = tid; i < N_ENTITY * N_REL; i += stride) g_deg[i] = 0;
    for (int i = tid; i < 2 * HPAD; i += stride) g_hist[i] = 0;
}

// ---------------------------------------------------------------------------
// degree per (dst,rel) + histograms per src and per dst (int atomics)
// ---------------------------------------------------------------------------
__global__ void k_hist(const int* __restrict__ edge_index, const int* __restrict__ edge_type) {
    int e = blockIdx.x * blockDim.x + threadIdx.x;
    if (e >= E_EDGES) return;
    int src = edge_index[e];
    int dst = edge_index[E_EDGES + e];
    int rel = edge_type[e];
    atomicAdd(&g_deg[dst * N_REL + rel], 1);
    atomicAdd(&g_hist[src], 1);
    atomicAdd(&g_hist[HPAD + dst], 1);
}

// ---------------------------------------------------------------------------
// three-phase exclusive scan over one histogram (sel = 0:src, 1:dst)
// ---------------------------------------------------------------------------
__global__ void k_scan1(int sel) {
    __shared__ int s[SCAN_BLK];
    int i = blockIdx.x * SCAN_BLK + threadIdx.x;
    s[threadIdx.x] = g_hist[sel * HPAD + i];
    __syncthreads();
    for (int o = SCAN_BLK / 2; o > 0; o >>= 1) {
        if (threadIdx.x < o) s[threadIdx.x] += s[threadIdx.x + o];
        __syncthreads();
    }
    if (threadIdx.x == 0) g_bsum[sel * SCAN_GRID + blockIdx.x] = s[0];
}

__global__ void k_scan2(int sel) {
    if (threadIdx.x == 0) {
        int acc = 0;
        for (int i = 0; i < SCAN_GRID; i++) {
            int v = g_bsum[sel * SCAN_GRID + i];
            g_bsum[sel * SCAN_GRID + i] = acc;
            acc += v;
        }
        if (sel == 0) g_offA[N_ENTITY] = E_EDGES;
        else          g_offB[N_ENTITY] = E_EDGES;
    }
}

__global__ void k_scan3(int sel) {
    __shared__ int s[SCAN_BLK];
    int i = blockIdx.x * SCAN_BLK + threadIdx.x;
    int v = g_hist[sel * HPAD + i];
    s[threadIdx.x] = v;
    __syncthreads();
    for (int o = 1; o < SCAN_BLK; o <<= 1) {
        int t = (threadIdx.x >= o) ? s[threadIdx.x - o] : 0;
        __syncthreads();
        s[threadIdx.x] += t;
        __syncthreads();
    }
    if (i < N_ENTITY) {
        int excl = g_bsum[sel * SCAN_GRID + blockIdx.x] + s[threadIdx.x] - v;
        if (sel == 0) { g_offA[i] = excl; g_cur[i] = excl; }
        else          { g_offB[i] = excl; g_cur[N_ENTITY + i] = excl; }
    }
}

// ---------------------------------------------------------------------------
// scatter: src-sorted edge metadata + each edge's dst-sorted message slot
// ---------------------------------------------------------------------------
__global__ void k_scatter(const int* __restrict__ edge_index, const int* __restrict__ edge_type) {
    int e = blockIdx.x * blockDim.x + threadIdx.x;
    if (e >= E_EDGES) return;
    int src = edge_index[e];
    int dst = edge_index[E_EDGES + e];
    int rel = edge_type[e];
    int p1 = atomicAdd(&g_cur[src], 1);
    int p2 = atomicAdd(&g_cur[N_ENTITY + dst], 1);
    g_edst[p1] = dst | (rel << 16);
    g_epos[p1] = p2;
}

// ---------------------------------------------------------------------------
// Pass 1: warp-per-src. Basis rows register-resident; write normalized
// message to its dst-sorted slot (plain 512B coalesced store, no atomics).
// ---------------------------------------------------------------------------
__global__ void __launch_bounds__(256) k_msg(const float* __restrict__ basis,
                                             const float* __restrict__ comp) {
    __shared__ float s_comp[N_REL * NBASES];
    for (int i = threadIdx.x; i < N_REL * NBASES; i += blockDim.x) s_comp[i] = comp[i];
    __syncthreads();

    int w = (blockIdx.x * blockDim.x + threadIdx.x) >> 5;   // src entity
    int lane = threadIdx.x & 31;
    if (w >= N_ENTITY) return;
    int n0 = g_offA[w], n1 = g_offA[w + 1];
    if (n0 == n1) return;

    const float4* bp = reinterpret_cast<const float4*>(basis) + (size_t)w * 32 + lane;
    float4 br[NBASES];
#pragma unroll
    for (int b = 0; b < NBASES; b++) br[b] = bp[(size_t)b * (N_ENTITY * 32)];

    for (int i = n0; i < n1; i++) {
        int packed = g_edst[i];
        int pos    = g_epos[i];
        int dst = packed & 0xFFFF;
        int rel = packed >> 16;
        float norm = 1.0f / (float)max(g_deg[dst * N_REL + rel], 1);
        const float* c = s_comp + rel * NBASES;
        float4 a;
        a.x = c[0] * br[0].x; a.y = c[0] * br[0].y; a.z = c[0] * br[0].z; a.w = c[0] * br[0].w;
#pragma unroll
        for (int b = 1; b < NBASES; b++) {
            float cb = c[b];
            a.x += cb * br[b].x; a.y += cb * br[b].y; a.z += cb * br[b].z; a.w += cb * br[b].w;
        }
        a.x *= norm; a.y *= norm; a.z *= norm; a.w *= norm;
        g_msg4[(size_t)pos * 32 + lane] = a;
    }
}

// ---------------------------------------------------------------------------
// Pass 2: warp-per-dst. Stream contiguous message run, accumulate in regs,
// write kg = root + bias + agg (single plain store).
// ---------------------------------------------------------------------------
__global__ void __launch_bounds__(256) k_agg(const float* __restrict__ root,
                                             const float* __restrict__ bias) {
    int d = (blockIdx.x * blockDim.x + threadIdx.x) >> 5;   // dst entity
    int lane = threadIdx.x & 31;
    if (d >= N_ENTITY) return;

    float4 acc = make_float4(0.f, 0.f, 0.f, 0.f);
    int n0 = g_offB[d], n1 = g_offB[d + 1];
    for (int i = n0; i < n1; i++) {
        float4 m = g_msg4[(size_t)i * 32 + lane];
        acc.x += m.x; acc.y += m.y; acc.z += m.z; acc.w += m.w;
    }
    float4 r = reinterpret_cast<const float4*>(root)[(size_t)d * 32 + lane];
    float4 bv = reinterpret_cast<const float4*>(bias)[lane];
    acc.x += r.x + bv.x; acc.y += r.y + bv.y; acc.z += r.z + bv.z; acc.w += r.w + bv.w;
    reinterpret_cast<float4*>(g_kg)[(size_t)d * 32 + lane] = acc;
}

// ---------------------------------------------------------------------------
// attention scores, one warp per (user, l)
// ---------------------------------------------------------------------------
__global__ void __launch_bounds__(256) k_score(const int* __restrict__ ctx,
                                               const float* __restrict__ attn_W,
                                               const float* __restrict__ attn_b) {
    int gw = (blockIdx.x * blockDim.x + threadIdx.x) >> 5;
    int lane = threadIdx.x & 31;
    if (gw >= B_USERS * L_CTX) return;

    int ent = ctx[gw];
    float4 h4 = reinterpret_cast<const float4*>(g_kg + (size_t)ent * DDIM)[lane];

    float u0 = 0.f, u1 = 0.f, u2 = 0.f, u3 = 0.f;
#pragma unroll 4
    for (int k = 0; k < DDIM; k++) {
        int sl = k >> 2, cp = k & 3;
        float hv = (cp == 0) ? h4.x : (cp == 1) ? h4.y : (cp == 2) ? h4.z : h4.w;
        float hk = __shfl_sync(0xFFFFFFFFu, hv, sl);
        const float* wr = attn_W + k * DDIM;
        u0 += hk * wr[lane];
        u1 += hk * wr[lane + 32];
        u2 += hk * wr[lane + 64];
        u3 += hk * wr[lane + 96];
    }
    float acc = tanhf(u0) * attn_b[lane] + tanhf(u1) * attn_b[lane + 32]
              + tanhf(u2) * attn_b[lane + 64] + tanhf(u3) * attn_b[lane + 96];
#pragma unroll
    for (int o = 16; o; o >>= 1) acc += __shfl_xor_sync(0xFFFFFFFFu, acc, o);
    if (lane == 0) g_sc[gw] = acc;
}

// ---------------------------------------------------------------------------
// per-user softmax + weighted sum + projection MLP (1 block/user)
// ---------------------------------------------------------------------------
__global__ void __launch_bounds__(DDIM) k_combine(const int* __restrict__ ctx,
                       const int* __restrict__ cmask,
                       const float* __restrict__ fc1_W, const float* __restrict__ fc1_b,
                       const float* __restrict__ fc2_W, const float* __restrict__ fc2_b,
                       float* __restrict__ out) {
    __shared__ float attn[L_CTX];
    __shared__ float urep[DDIM];
    __shared__ float yv[DDIM];

    int b = blockIdx.x;
    int t = threadIdx.x;

    if (t == 0) {
        float mx = -3.4e38f; bool any = false;
        for (int l = 0; l < L_CTX; l++)
            if (cmask[b * L_CTX + l]) { any = true; mx = fmaxf(mx, g_sc[b * L_CTX + l]); }
        float s = 0.f;
        for (int l = 0; l < L_CTX; l++) {
            float v = cmask[b * L_CTX + l] ? expf(g_sc[b * L_CTX + l] - mx) : 0.f;
            attn[l] = v; s += v;
        }
        float inv = any ? 1.f / s : 0.f;
        for (int l = 0; l < L_CTX; l++) attn[l] *= inv;
    }
    __syncthreads();

    float r = 0.f;
    for (int l = 0; l < L_CTX; l++) {
        int ent = ctx[b * L_CTX + l];
        r += attn[l] * g_kg[(size_t)ent * DDIM + t];
    }
    urep[t] = r;
    __syncthreads();

    float y = fc1_b[t];
    for (int k = 0; k < DDIM; k++) y += urep[k] * fc1_W[k * DDIM + t];
    yv[t] = fmaxf(y, 0.f);
    __syncthreads();

    float o = fc2_b[t];
    for (int k = 0; k < DDIM; k++) o += yv[k] * fc2_W[k * DDIM + t];
    out[b * DDIM + t] = o;
}

// ---------------------------------------------------------------------------
// entity gather + projection MLP (1 block/entity)
// ---------------------------------------------------------------------------
__global__ void __launch_bounds__(DDIM) k_entity(const int* __restrict__ entity_ids,
                         const float* __restrict__ efc1_W, const float* __restrict__ efc1_b,
                         const float* __restrict__ efc2_W, const float* __restrict__ efc2_b,
                         float* __restrict__ out) {
    __shared__ float x[DDIM];
    __shared__ float yv[DDIM];
    int i = blockIdx.x;
    int t = threadIdx.x;

    int ent = entity_ids[i];
    x[t] = g_kg[(size_t)ent * DDIM + t];
    __syncthreads();

    float y = efc1_b[t];
    for (int k = 0; k < DDIM; k++) y += x[k] * efc1_W[k * DDIM + t];
    yv[t] = fmaxf(y, 0.f);
    __syncthreads();

    float o = efc2_b[t];
    for (int k = 0; k < DDIM; k++) o += yv[k] * efc2_W[k * DDIM + t];
    out[B_USERS * DDIM + i * DDIM + t] = o;
}

// ---------------------------------------------------------------------------
extern "C" void kernel_launch(void* const* d_in, const int* in_sizes, int n_in,
                              void* d_out, int out_size) {
    const int*   edge_index = (const int*)d_in[0];
    const int*   edge_type  = (const int*)d_in[1];
    const int*   ctx        = (const int*)d_in[2];
    const int*   cmask      = (const int*)d_in[3];
    const int*   entity_ids = (const int*)d_in[4];
    const float* comp       = (const float*)d_in[5];
    const float* basis      = (const float*)d_in[6];
    const float* root       = (const float*)d_in[7];
    const float* bias       = (const float*)d_in[8];
    const float* attn_W     = (const float*)d_in[9];
    const float* attn_b     = (const float*)d_in[10];
    const float* fc1_W      = (const float*)d_in[11];
    const float* fc1_b      = (const float*)d_in[12];
    const float* fc2_W      = (const float*)d_in[13];
    const float* fc2_b      = (const float*)d_in[14];
    const float* efc1_W     = (const float*)d_in[15];
    const float* efc1_b     = (const float*)d_in[16];
    const float* efc2_W     = (const float*)d_in[17];
    const float* efc2_b     = (const float*)d_in[18];
    float* out = (float*)d_out;

    k_init<<<512, 256>>>();
    k_hist<<<(E_EDGES + 255) / 256, 256>>>(edge_index, edge_type);
    k_scan1<<<SCAN_GRID, SCAN_BLK>>>(0);
    k_scan1<<<SCAN_GRID, SCAN_BLK>>>(1);
    k_scan2<<<1, 32>>>(0);
    k_scan2<<<1, 32>>>(1);
    k_scan3<<<SCAN_GRID, SCAN_BLK>>>(0);
    k_scan3<<<SCAN_GRID, SCAN_BLK>>>(1);
    k_scatter<<<(E_EDGES + 255) / 256, 256>>>(edge_index, edge_type);
    k_msg<<<(N_ENTITY * 32 + 255) / 256, 256>>>(basis, comp);
    k_agg<<<(N_ENTITY * 32 + 255) / 256, 256>>>(root, bias);
    k_score<<<(B_USERS * L_CTX * 32 + 255) / 256, 256>>>(ctx, attn_W, attn_b);
    k_combine<<<B_USERS, DDIM>>>(ctx, cmask, fc1_W, fc1_b, fc2_W, fc2_b, out);
    k_entity<<<NE_ENT, DDIM>>>(entity_ids, efc1_W, efc1_b, efc2_W, efc2_b, out);
}

// round 6
// speedup vs baseline: 4.1774x; 2.5645x over previous
#include <cuda_runtime.h>
#include <cuda_bf16.h>
#include <math.h>

#define N_ENTITY 64368
#define N_REL    46
#define NBASES   8
#define DDIM     128
#define E_EDGES  600000
#define B_USERS  64
#define L_CTX    50
#define NE_ENT   256

#define SCAN_BLK   256
#define SCAN_GRID  ((N_ENTITY + SCAN_BLK - 1) / SCAN_BLK)   // 252
#define HPAD       (SCAN_GRID * SCAN_BLK)                   // 64512
#define MMAX       4096                                     // >= B*L + NE = 3456

// ---- device-global scratch (allocation forbidden; int atomics only) ----
__device__ int   g_flag[HPAD];             // needed-entity flags (0/1)
__device__ int   g_slot[N_ENTITY];         // entity -> compact slot (-1 if unused)
__device__ int   g_ent[MMAX];              // slot -> entity
__device__ int   g_M;                      // number of used slots
__device__ int   g_bsum[SCAN_GRID];        // flag-scan partials
__device__ int   g_hist2[MMAX];            // relevant edges per slot
__device__ int   g_eoff[MMAX + 1];         // slot-sorted edge offsets
__device__ int   g_cur2[MMAX];             // scatter cursors
__device__ int   g_deg2[MMAX * N_REL];     // per-(slot,rel) degree
__device__ int   g_elist[E_EDGES];         // slot-sorted edges: src | (rel<<17)
__device__ __align__(16) float g_kgc[MMAX * DDIM];  // 2 MB compact kg_emb
__device__ float g_sc[B_USERS * L_CTX];    // attention scores

// ---------------------------------------------------------------------------
// zero flags, hist, deg
// ---------------------------------------------------------------------------
__global__ void k_init() {
    const int stride = gridDim.x * blockDim.x;
    const int tid = blockIdx.x * blockDim.x + threadIdx.x;
    for (int i = tid; i < HPAD; i += stride) g_flag[i] = 0;
    for (int i = tid; i < MMAX; i += stride) g_hist2[i] = 0;
    for (int i = tid; i < MMAX * N_REL; i += stride) g_deg2[i] = 0;
}

// ---------------------------------------------------------------------------
// mark needed entities (ctx union entity_ids); duplicate stores are fine
// ---------------------------------------------------------------------------
__global__ void k_mark(const int* __restrict__ ctx, const int* __restrict__ entity_ids) {
    int t = blockIdx.x * blockDim.x + threadIdx.x;
    if (t < B_USERS * L_CTX) g_flag[ctx[t]] = 1;
    if (t < NE_ENT)          g_flag[entity_ids[t]] = 1;
}

// ---------------------------------------------------------------------------
// flag scan phase 1: per-block sums
// ---------------------------------------------------------------------------
__global__ void f_scan1() {
    __shared__ int s[SCAN_BLK];
    int i = blockIdx.x * SCAN_BLK + threadIdx.x;
    s[threadIdx.x] = g_flag[i];
    __syncthreads();
    for (int o = SCAN_BLK / 2; o > 0; o >>= 1) {
        if (threadIdx.x < o) s[threadIdx.x] += s[threadIdx.x + o];
        __syncthreads();
    }
    if (threadIdx.x == 0) g_bsum[blockIdx.x] = s[0];
}

// ---------------------------------------------------------------------------
// flag scan phase 2: parallel exclusive scan of 252 block sums (1 block)
// ---------------------------------------------------------------------------
__global__ void f_scan2() {
    __shared__ int sh[SCAN_BLK];
    int t = threadIdx.x;
    int v = (t < SCAN_GRID) ? g_bsum[t] : 0;
    sh[t] = v;
    __syncthreads();
    for (int o = 1; o < SCAN_BLK; o <<= 1) {
        int a = (t >= o) ? sh[t - o] : 0;
        __syncthreads();
        sh[t] += a;
        __syncthreads();
    }
    if (t < SCAN_GRID) g_bsum[t] = sh[t] - v;
    if (t == SCAN_BLK - 1) g_M = sh[SCAN_BLK - 1];
}

// ---------------------------------------------------------------------------
// flag scan phase 3: assign slots + reverse map
// ---------------------------------------------------------------------------
__global__ void f_scan3() {
    __shared__ int s[SCAN_BLK];
    int i = blockIdx.x * SCAN_BLK + threadIdx.x;
    int v = g_flag[i];
    s[threadIdx.x] = v;
    __syncthreads();
    for (int o = 1; o < SCAN_BLK; o <<= 1) {
        int a = (threadIdx.x >= o) ? s[threadIdx.x - o] : 0;
        __syncthreads();
        s[threadIdx.x] += a;
        __syncthreads();
    }
    if (i < N_ENTITY) {
        int excl = g_bsum[blockIdx.x] + s[threadIdx.x] - v;
        if (v) { g_slot[i] = excl; g_ent[excl] = i; }
        else   { g_slot[i] = -1; }
    }
}

// ---------------------------------------------------------------------------
// edge pass 1: hist + degree for edges into needed dsts
// ---------------------------------------------------------------------------
__global__ void k_ehist(const int* __restrict__ edge_index, const int* __restrict__ edge_type) {
    int e = blockIdx.x * blockDim.x + threadIdx.x;
    if (e >= E_EDGES) return;
    int dst = edge_index[E_EDGES + e];
    int s = g_slot[dst];
    if (s < 0) return;
    int rel = edge_type[e];
    atomicAdd(&g_hist2[s], 1);
    atomicAdd(&g_deg2[s * N_REL + rel], 1);
}

// ---------------------------------------------------------------------------
// slot-edge scan: 1 block, 1024 threads, 4 elements each over MMAX=4096
// ---------------------------------------------------------------------------
__global__ void k_escan() {
    __shared__ int sh[1024];
    int t = threadIdx.x;
    int v[4]; int sum = 0;
#pragma unroll
    for (int j = 0; j < 4; j++) { v[j] = g_hist2[t * 4 + j]; sum += v[j]; }
    sh[t] = sum;
    __syncthreads();
    for (int o = 1; o < 1024; o <<= 1) {
        int a = (t >= o) ? sh[t - o] : 0;
        __syncthreads();
        sh[t] += a;
        __syncthreads();
    }
    int excl = sh[t] - sum;
#pragma unroll
    for (int j = 0; j < 4; j++) {
        g_eoff[t * 4 + j] = excl;
        g_cur2[t * 4 + j] = excl;
        excl += v[j];
    }
    if (t == 1023) g_eoff[MMAX] = excl;
}

// ---------------------------------------------------------------------------
// edge pass 2: scatter relevant edges into slot-sorted order
// ---------------------------------------------------------------------------
__global__ void k_escatter(const int* __restrict__ edge_index, const int* __restrict__ edge_type) {
    int e = blockIdx.x * blockDim.x + threadIdx.x;
    if (e >= E_EDGES) return;
    int dst = edge_index[E_EDGES + e];
    int s = g_slot[dst];
    if (s < 0) return;
    int src = edge_index[e];
    int rel = edge_type[e];
    int pos = atomicAdd(&g_cur2[s], 1);
    g_elist[pos] = src | (rel << 17);       // src < 2^17, rel < 2^6
}

// ---------------------------------------------------------------------------
// aggregation: warp per needed slot; gather basis rows directly.
// kg = root + bias + sum_edges norm * sum_b comp[rel,b] * basis[b][src]
// ---------------------------------------------------------------------------
__global__ void __launch_bounds__(256) k_agg(const float* __restrict__ basis,
                                             const float* __restrict__ comp,
                                             const float* __restrict__ root,
                                             const float* __restrict__ bias) {
    __shared__ float s_comp[N_REL * NBASES];
    for (int i = threadIdx.x; i < N_REL * NBASES; i += blockDim.x) s_comp[i] = comp[i];
    __syncthreads();

    int slot = (blockIdx.x * blockDim.x + threadIdx.x) >> 5;
    int lane = threadIdx.x & 31;
    if (slot >= g_M) return;

    int ent = g_ent[slot];
    float4 acc = reinterpret_cast<const float4*>(root)[(size_t)ent * 32 + lane];
    float4 bv  = reinterpret_cast<const float4*>(bias)[lane];
    acc.x += bv.x; acc.y += bv.y; acc.z += bv.z; acc.w += bv.w;

    int n0 = g_eoff[slot], n1 = g_eoff[slot + 1];
    for (int i = n0; i < n1; i++) {
        int packed = g_elist[i];                 // warp-broadcast load
        int src = packed & 0x1FFFF;
        int rel = packed >> 17;
        float norm = 1.0f / (float)max(g_deg2[slot * N_REL + rel], 1);
        const float* c = s_comp + rel * NBASES;
        const float4* bp = reinterpret_cast<const float4*>(basis) + (size_t)src * 32 + lane;
        // issue all 8 gathers, then reduce
        float4 br[NBASES];
#pragma unroll
        for (int b = 0; b < NBASES; b++) br[b] = bp[(size_t)b * (N_ENTITY * 32)];
        float4 m;
        m.x = c[0] * br[0].x; m.y = c[0] * br[0].y; m.z = c[0] * br[0].z; m.w = c[0] * br[0].w;
#pragma unroll
        for (int b = 1; b < NBASES; b++) {
            float cb = c[b];
            m.x += cb * br[b].x; m.y += cb * br[b].y; m.z += cb * br[b].z; m.w += cb * br[b].w;
        }
        acc.x += norm * m.x; acc.y += norm * m.y; acc.z += norm * m.z; acc.w += norm * m.w;
    }
    reinterpret_cast<float4*>(g_kgc)[(size_t)slot * 32 + lane] = acc;
}

// ---------------------------------------------------------------------------
// attention scores, one warp per (user, l); kg read via slot map (L2-hot)
// ---------------------------------------------------------------------------
__global__ void __launch_bounds__(256) k_score(const int* __restrict__ ctx,
                                               const float* __restrict__ attn_W,
                                               const float* __restrict__ attn_b) {
    int gw = (blockIdx.x * blockDim.x + threadIdx.x) >> 5;
    int lane = threadIdx.x & 31;
    if (gw >= B_USERS * L_CTX) return;

    int slot = g_slot[ctx[gw]];
    float4 h4 = reinterpret_cast<const float4*>(g_kgc + (size_t)slot * DDIM)[lane];

    float u0 = 0.f, u1 = 0.f, u2 = 0.f, u3 = 0.f;
#pragma unroll 4
    for (int k = 0; k < DDIM; k++) {
        int sl = k >> 2, cp = k & 3;
        float hv = (cp == 0) ? h4.x : (cp == 1) ? h4.y : (cp == 2) ? h4.z : h4.w;
        float hk = __shfl_sync(0xFFFFFFFFu, hv, sl);
        const float* wr = attn_W + k * DDIM;
        u0 += hk * wr[lane];
        u1 += hk * wr[lane + 32];
        u2 += hk * wr[lane + 64];
        u3 += hk * wr[lane + 96];
    }
    float acc = tanhf(u0) * attn_b[lane] + tanhf(u1) * attn_b[lane + 32]
              + tanhf(u2) * attn_b[lane + 64] + tanhf(u3) * attn_b[lane + 96];
#pragma unroll
    for (int o = 16; o; o >>= 1) acc += __shfl_xor_sync(0xFFFFFFFFu, acc, o);
    if (lane == 0) g_sc[gw] = acc;
}

// ---------------------------------------------------------------------------
// per-user softmax + weighted sum + projection MLP (1 block/user)
// ---------------------------------------------------------------------------
__global__ void __launch_bounds__(DDIM) k_combine(const int* __restrict__ ctx,
                       const int* __restrict__ cmask,
                       const float* __restrict__ fc1_W, const float* __restrict__ fc1_b,
                       const float* __restrict__ fc2_W, const float* __restrict__ fc2_b,
                       float* __restrict__ out) {
    __shared__ float attn[L_CTX];
    __shared__ float urep[DDIM];
    __shared__ float yv[DDIM];

    int b = blockIdx.x;
    int t = threadIdx.x;

    if (t == 0) {
        float mx = -3.4e38f; bool any = false;
        for (int l = 0; l < L_CTX; l++)
            if (cmask[b * L_CTX + l]) { any = true; mx = fmaxf(mx, g_sc[b * L_CTX + l]); }
        float s = 0.f;
        for (int l = 0; l < L_CTX; l++) {
            float v = cmask[b * L_CTX + l] ? expf(g_sc[b * L_CTX + l] - mx) : 0.f;
            attn[l] = v; s += v;
        }
        float inv = any ? 1.f / s : 0.f;
        for (int l = 0; l < L_CTX; l++) attn[l] *= inv;
    }
    __syncthreads();

    float r = 0.f;
    for (int l = 0; l < L_CTX; l++) {
        int slot = g_slot[ctx[b * L_CTX + l]];
        r += attn[l] * g_kgc[(size_t)slot * DDIM + t];
    }
    urep[t] = r;
    __syncthreads();

    float y = fc1_b[t];
    for (int k = 0; k < DDIM; k++) y += urep[k] * fc1_W[k * DDIM + t];
    yv[t] = fmaxf(y, 0.f);
    __syncthreads();

    float o = fc2_b[t];
    for (int k = 0; k < DDIM; k++) o += yv[k] * fc2_W[k * DDIM + t];
    out[b * DDIM + t] = o;
}

// ---------------------------------------------------------------------------
// entity gather + projection MLP (1 block/entity)
// ---------------------------------------------------------------------------
__global__ void __launch_bounds__(DDIM) k_entity(const int* __restrict__ entity_ids,
                         const float* __restrict__ efc1_W, const float* __restrict__ efc1_b,
                         const float* __restrict__ efc2_W, const float* __restrict__ efc2_b,
                         float* __restrict__ out) {
    __shared__ float x[DDIM];
    __shared__ float yv[DDIM];
    int i = blockIdx.x;
    int t = threadIdx.x;

    int slot = g_slot[entity_ids[i]];
    x[t] = g_kgc[(size_t)slot * DDIM + t];
    __syncthreads();

    float y = efc1_b[t];
    for (int k = 0; k < DDIM; k++) y += x[k] * efc1_W[k * DDIM + t];
    yv[t] = fmaxf(y, 0.f);
    __syncthreads();

    float o = efc2_b[t];
    for (int k = 0; k < DDIM; k++) o += yv[k] * efc2_W[k * DDIM + t];
    out[B_USERS * DDIM + i * DDIM + t] = o;
}

// ---------------------------------------------------------------------------
extern "C" void kernel_launch(void* const* d_in, const int* in_sizes, int n_in,
                              void* d_out, int out_size) {
    const int*   edge_index = (const int*)d_in[0];
    const int*   edge_type  = (const int*)d_in[1];
    const int*   ctx        = (const int*)d_in[2];
    const int*   cmask      = (const int*)d_in[3];
    const int*   entity_ids = (const int*)d_in[4];
    const float* comp       = (const float*)d_in[5];
    const float* basis      = (const float*)d_in[6];
    const float* root       = (const float*)d_in[7];
    const float* bias       = (const float*)d_in[8];
    const float* attn_W     = (const float*)d_in[9];
    const float* attn_b     = (const float*)d_in[10];
    const float* fc1_W      = (const float*)d_in[11];
    const float* fc1_b      = (const float*)d_in[12];
    const float* fc2_W      = (const float*)d_in[13];
    const float* fc2_b      = (const float*)d_in[14];
    const float* efc1_W     = (const float*)d_in[15];
    const float* efc1_b     = (const float*)d_in[16];
    const float* efc2_W     = (const float*)d_in[17];
    const float* efc2_b     = (const float*)d_in[18];
    float* out = (float*)d_out;

    k_init<<<256, 256>>>();
    k_mark<<<(B_USERS * L_CTX + 255) / 256, 256>>>(ctx, entity_ids);
    f_scan1<<<SCAN_GRID, SCAN_BLK>>>();
    f_scan2<<<1, SCAN_BLK>>>();
    f_scan3<<<SCAN_GRID, SCAN_BLK>>>();
    k_ehist<<<(E_EDGES + 255) / 256, 256>>>(edge_index, edge_type);
    k_escan<<<1, 1024>>>();
    k_escatter<<<(E_EDGES + 255) / 256, 256>>>(edge_index, edge_type);
    k_agg<<<(MMAX * 32) / 256, 256>>>(basis, comp, root, bias);
    k_score<<<(B_USERS * L_CTX * 32 + 255) / 256, 256>>>(ctx, attn_W, attn_b);
    k_combine<<<B_USERS, DDIM>>>(ctx, cmask, fc1_W, fc1_b, fc2_W, fc2_b, out);
    k_entity<<<NE_ENT, DDIM>>>(entity_ids, efc1_W, efc1_b, efc2_W, efc2_b, out);
}